// round 1
// baseline (speedup 1.0000x reference)
#include <cuda_runtime.h>
#include <math.h>

// Problem constants
constexpr int B = 8, T = 8, H = 14, W = 14;
constexpr int P = T * H * W;     // 1568
constexpr int N = B * P;         // 12544
constexpr float BN_EPS = 1e-5f;

// ---------------------------------------------------------------------------
// Scratch (no allocations allowed -> __device__ globals)
// ---------------------------------------------------------------------------
__device__ float g_samp[54190080];  // max Cin*K*N = 4320*12544 (layer2), reused as im2col
__device__ float g_off[1016064];    // max 3K*N = 81*12544
__device__ float g_outb[4014080];   // max Cout*N = 320*12544
__device__ float g_t1[2007040];     // branch1 mid act: B*160*P
__device__ float g_t3[401408];      // branch2 mid act: B*32*P
__device__ float g_xm[10436608];    // maxpool: B*832*P
__device__ float g_mean[320];
__device__ float g_var[320];

// ---------------------------------------------------------------------------
// im2col: COL[(c*K+tap)][n] = Xpad[b][c][t-pad+kt][h-pad+kh][w-pad+kw]
// X layout: [B][Cin][P].  n = b*P + p.
// ---------------------------------------------------------------------------
__global__ void im2col_k(const float* __restrict__ X, float* __restrict__ COL,
                         int Cin, int kc, int pad, int total) {
    int idx = blockIdx.x * blockDim.x + threadIdx.x;
    if (idx >= total) return;
    int n = idx % N;
    int ck = idx / N;
    int K = kc * kc * kc;
    int tap = ck % K;
    int c = ck / K;
    int b = n / P, p = n % P;
    int t = p / (H * W), h = (p / W) % H, w = p % W;
    int kt = tap / (kc * kc), kh = (tap / kc) % kc, kw = tap % kc;
    int tz = t - pad + kt, hy = h - pad + kh, wx = w - pad + kw;
    float v = 0.f;
    if (tz >= 0 && tz < T && hy >= 0 && hy < H && wx >= 0 && wx < W)
        v = X[(b * Cin + c) * P + (tz * H + hy) * W + wx];
    COL[idx] = v;
}

// ---------------------------------------------------------------------------
// SGEMM: C[M][N] = A[M][Kd] * Bm[Kd][N] (+ bias[M]).
// Requires Kd % 16 == 0 (true here: 832, 864, 4320) and N % 64 == 0 (12544).
// 64x64 tile, BK=16, 256 threads, 4x4 microtile, float4 global/shared traffic.
// ---------------------------------------------------------------------------
__global__ __launch_bounds__(256) void sgemm_k(
    const float* __restrict__ A, const float* __restrict__ Bm,
    const float* __restrict__ bias, float* __restrict__ C, int M, int Kd) {
    constexpr int BK = 16;
    __shared__ float As[BK][68];  // [k][m], stride 68 floats = 272B (16B aligned rows)
    __shared__ float Bs[BK][68];  // [k][n]

    int tid = threadIdx.x;
    int tx = tid & 15, ty = tid >> 4;
    int bm = blockIdx.y * 64, bn = blockIdx.x * 64;

    // A tile loader: 64 rows x 16 k.  thread -> row = tid>>2, kcol = (tid&3)*4
    int aRow = tid >> 2, aCol = (tid & 3) * 4;
    // B tile loader: 16 k x 64 cols. thread -> krow = tid>>4, ncol = (tid&15)*4
    int bRow = tid >> 4, bCol = (tid & 15) * 4;

    float acc[4][4] = {};

    for (int k0 = 0; k0 < Kd; k0 += BK) {
        int m = bm + aRow;
        float4 a4 = make_float4(0.f, 0.f, 0.f, 0.f);
        if (m < M)
            a4 = *reinterpret_cast<const float4*>(&A[(size_t)m * Kd + k0 + aCol]);
        As[aCol + 0][aRow] = a4.x;
        As[aCol + 1][aRow] = a4.y;
        As[aCol + 2][aRow] = a4.z;
        As[aCol + 3][aRow] = a4.w;

        float4 b4 = *reinterpret_cast<const float4*>(
            &Bm[(size_t)(k0 + bRow) * N + bn + bCol]);
        *reinterpret_cast<float4*>(&Bs[bRow][bCol]) = b4;

        __syncthreads();

#pragma unroll
        for (int kk = 0; kk < BK; kk++) {
            float4 av = *reinterpret_cast<float4*>(&As[kk][ty * 4]);
            float4 bv = *reinterpret_cast<float4*>(&Bs[kk][tx * 4]);
            float a[4] = {av.x, av.y, av.z, av.w};
            float b[4] = {bv.x, bv.y, bv.z, bv.w};
#pragma unroll
            for (int i = 0; i < 4; i++)
#pragma unroll
                for (int j = 0; j < 4; j++) acc[i][j] += a[i] * b[j];
        }
        __syncthreads();
    }

#pragma unroll
    for (int i = 0; i < 4; i++) {
        int m = bm + ty * 4 + i;
        if (m >= M) continue;
        float bv = bias ? bias[m] : 0.f;
        float4 o = make_float4(acc[i][0] + bv, acc[i][1] + bv,
                               acc[i][2] + bv, acc[i][3] + bv);
        *reinterpret_cast<float4*>(&C[(size_t)m * N + bn + tx * 4]) = o;
    }
}

// ---------------------------------------------------------------------------
// Deformable trilinear sampling.
// OFF layout [3K][N] (GEMM output), channel j = k*3 + d (d: 0=t,1=h,2=w).
// SAMP[(c*K + k)][n] = sum_corners wgt * X[b][c][corner]
// grid: (ceil(N/128), K), block 128.
// ---------------------------------------------------------------------------
__global__ __launch_bounds__(128) void dsample_k(
    const float* __restrict__ X, const float* __restrict__ OFF,
    float* __restrict__ SAMP, int Cin, int kc, int pad) {
    int n = blockIdx.x * blockDim.x + threadIdx.x;
    if (n >= N) return;
    int k = blockIdx.y;
    int K = kc * kc * kc;
    int b = n / P, p = n % P;
    int t = p / (H * W), h = (p / W) % H, w = p % W;
    int kt = k / (kc * kc), kh = (k / kc) % kc, kw = k % kc;

    float tc = (float)(t - pad + kt) + OFF[(size_t)(k * 3 + 0) * N + n];
    float hc = (float)(h - pad + kh) + OFF[(size_t)(k * 3 + 1) * N + n];
    float wc = (float)(w - pad + kw) + OFF[(size_t)(k * 3 + 2) * N + n];
    float t0 = floorf(tc), h0 = floorf(hc), w0 = floorf(wc);

    int lin[8];
    float wg[8];
#pragma unroll
    for (int d = 0; d < 8; d++) {
        float ti = t0 + (float)(d >> 2);
        float hi = h0 + (float)((d >> 1) & 1);
        float wi = w0 + (float)(d & 1);
        float wgt = (1.f - fabsf(tc - ti)) * (1.f - fabsf(hc - hi)) *
                    (1.f - fabsf(wc - wi));
        bool valid = (ti >= 0.f) && (ti < (float)T) && (hi >= 0.f) &&
                     (hi < (float)H) && (wi >= 0.f) && (wi < (float)W);
        wg[d] = valid ? wgt : 0.f;
        int it = min(max((int)ti, 0), T - 1);
        int ih = min(max((int)hi, 0), H - 1);
        int iw = min(max((int)wi, 0), W - 1);
        lin[d] = (it * H + ih) * W + iw;
    }

    const float* xb = X + (size_t)b * Cin * P;
    float* sp = SAMP + (size_t)k * N + n;
    size_t cstride = (size_t)K * N;
    for (int c = 0; c < Cin; c++) {
        const float* xc = xb + c * P;
        float v = 0.f;
#pragma unroll
        for (int d = 0; d < 8; d++) v += wg[d] * xc[lin[d]];
        sp[(size_t)c * cstride] = v;
    }
}

// ---------------------------------------------------------------------------
// MaxPool3d 3x3x3 stride 1 pad 1 over [B*C][P]
// ---------------------------------------------------------------------------
__global__ void maxpool_k(const float* __restrict__ X, float* __restrict__ Y,
                          int totBC) {
    int idx = blockIdx.x * blockDim.x + threadIdx.x;
    if (idx >= totBC * P) return;
    int p = idx % P;
    int bc = idx / P;
    int t = p / (H * W), h = (p / W) % H, w = p % W;
    const float* xb = X + (size_t)bc * P;
    float m = -INFINITY;
    for (int dt = -1; dt <= 1; dt++) {
        int tz = t + dt;
        if (tz < 0 || tz >= T) continue;
        for (int dh = -1; dh <= 1; dh++) {
            int hy = h + dh;
            if (hy < 0 || hy >= H) continue;
            for (int dw = -1; dw <= 1; dw++) {
                int wx = w + dw;
                if (wx < 0 || wx >= W) continue;
                m = fmaxf(m, xb[(tz * H + hy) * W + wx]);
            }
        }
    }
    Y[idx] = m;
}

// ---------------------------------------------------------------------------
// BN batch stats per channel (biased var), one block per channel.
// ---------------------------------------------------------------------------
__global__ __launch_bounds__(256) void bnstats_k(const float* __restrict__ OUT,
                                                 float* __restrict__ mean,
                                                 float* __restrict__ var) {
    int o = blockIdx.x;
    const float* row = OUT + (size_t)o * N;
    float s = 0.f, sq = 0.f;
    for (int n = threadIdx.x; n < N; n += blockDim.x) {
        float v = row[n];
        s += v;
        sq += v * v;
    }
    __shared__ float ss[256], sqq[256];
    ss[threadIdx.x] = s;
    sqq[threadIdx.x] = sq;
    __syncthreads();
    for (int st = 128; st > 0; st >>= 1) {
        if (threadIdx.x < st) {
            ss[threadIdx.x] += ss[threadIdx.x + st];
            sqq[threadIdx.x] += sqq[threadIdx.x + st];
        }
        __syncthreads();
    }
    if (threadIdx.x == 0) {
        float m = ss[0] / (float)N;
        mean[o] = m;
        var[o] = sqq[0] / (float)N - m * m;
    }
}

// ---------------------------------------------------------------------------
// BN apply + ReLU; writes dst[b][c0+o][p] with channel-dim dstC.
// ---------------------------------------------------------------------------
__global__ void bnapply_k(const float* __restrict__ OUT,
                          const float* __restrict__ mean,
                          const float* __restrict__ var,
                          const float* __restrict__ gamma,
                          const float* __restrict__ beta,
                          float* __restrict__ dst, int Cout, int dstC, int c0) {
    int idx = blockIdx.x * blockDim.x + threadIdx.x;
    if (idx >= Cout * N) return;
    int o = idx / N;
    int n = idx % N;
    int b = n / P, p = n % P;
    float inv = rsqrtf(var[o] + BN_EPS);
    float v = gamma[o] * (OUT[idx] - mean[o]) * inv + beta[o];
    dst[((size_t)b * dstC + c0 + o) * P + p] = fmaxf(v, 0.f);
}

// ---------------------------------------------------------------------------
// Host-side orchestration (all launches on the capture stream, ordered).
// ---------------------------------------------------------------------------
static void run_deform(const float* Xin, int Cin, int Cout, int kc, int pad,
                       const float* woff, const float* boff, const float* wmain,
                       const float* gamma, const float* beta, float* dst,
                       int dstC, int c0, float* samp, float* off, float* outb,
                       float* mean, float* var) {
    int K = kc * kc * kc;
    int Kd = Cin * K;

    // 1. im2col for offset conv
    int total = Kd * N;
    im2col_k<<<(total + 255) / 256, 256>>>(Xin, samp, Cin, kc, pad, total);

    // 2. offset conv GEMM: OFF[3K][N] = woff[3K][Kd] @ COL + boff
    {
        dim3 g(N / 64, (3 * K + 63) / 64);
        sgemm_k<<<g, 256>>>(woff, samp, boff, off, 3 * K, Kd);
    }

    // 3. deformable trilinear sampling (overwrites samp buffer)
    {
        dim3 g((N + 127) / 128, K);
        dsample_k<<<g, 128>>>(Xin, off, samp, Cin, kc, pad);
    }

    // 4. main GEMM: OUT[Cout][N] = w[Cout][Kd] @ SAMP
    {
        dim3 g(N / 64, (Cout + 63) / 64);
        sgemm_k<<<g, 256>>>(wmain, samp, nullptr, outb, Cout, Kd);
    }

    // 5. BN stats + apply + ReLU
    bnstats_k<<<Cout, 256>>>(outb, mean, var);
    int tot2 = Cout * N;
    bnapply_k<<<(tot2 + 255) / 256, 256>>>(outb, mean, var, gamma, beta, dst,
                                           Cout, dstC, c0);
}

extern "C" void kernel_launch(void* const* d_in, const int* in_sizes, int n_in,
                              void* d_out, int out_size) {
    const float* x = (const float*)d_in[0];
    float* out = (float*)d_out;

    float *samp, *off, *outb, *t1, *t3, *xm, *mean, *var;
    cudaGetSymbolAddress((void**)&samp, g_samp);
    cudaGetSymbolAddress((void**)&off, g_off);
    cudaGetSymbolAddress((void**)&outb, g_outb);
    cudaGetSymbolAddress((void**)&t1, g_t1);
    cudaGetSymbolAddress((void**)&t3, g_t3);
    cudaGetSymbolAddress((void**)&xm, g_xm);
    cudaGetSymbolAddress((void**)&mean, g_mean);
    cudaGetSymbolAddress((void**)&var, g_var);

    // params for layer i at d_in[1+5i .. 5+5i]: woff, boff, w, gamma, beta
    auto L = [&](int i, int j) { return (const float*)d_in[1 + 5 * i + j]; };

    // branch0: x0 = deform(x, 832->256, k1) -> out channels [0,256)
    run_deform(x, 832, 256, 1, 0, L(0, 0), L(0, 1), L(0, 2), L(0, 3), L(0, 4),
               out, 832, 0, samp, off, outb, mean, var);

    // branch1: t1 = deform(x, 832->160, k1); x1 = deform(t1, 160->320, k3,p1)
    run_deform(x, 832, 160, 1, 0, L(1, 0), L(1, 1), L(1, 2), L(1, 3), L(1, 4),
               t1, 160, 0, samp, off, outb, mean, var);
    run_deform(t1, 160, 320, 3, 1, L(2, 0), L(2, 1), L(2, 2), L(2, 3), L(2, 4),
               out, 832, 256, samp, off, outb, mean, var);

    // branch2: t3 = deform(x, 832->32, k1); x2 = deform(t3, 32->128, k3,p1)
    run_deform(x, 832, 32, 1, 0, L(3, 0), L(3, 1), L(3, 2), L(3, 3), L(3, 4),
               t3, 32, 0, samp, off, outb, mean, var);
    run_deform(t3, 32, 128, 3, 1, L(4, 0), L(4, 1), L(4, 2), L(4, 3), L(4, 4),
               out, 832, 576, samp, off, outb, mean, var);

    // branch3: xm = maxpool3d(x); x3 = deform(xm, 832->128, k1)
    maxpool_k<<<(B * 832 * P + 255) / 256, 256>>>(x, xm, B * 832);
    run_deform(xm, 832, 128, 1, 0, L(5, 0), L(5, 1), L(5, 2), L(5, 3), L(5, 4),
               out, 832, 704, samp, off, outb, mean, var);
}